// round 12
// baseline (speedup 1.0000x reference)
#include <cuda_runtime.h>
#include <cuda_fp16.h>

// Trilinear interpolation, fp16 cell-table + cp.async gathers (R9 geometry):
//   Pass 1 (repack): y (8,64^3 f32) -> g_tab (8, 63,63, 64-pad cells x 8 fp16
//           corners, 16 B/cell; z padded to 64: branch-free line-aligned
//           stores, shift-based indexing in interp).
//   Pass 2 (interp): 4 points/thread, 1.77M threads (occupancy is king for
//           this random gather: R10 showed 8pts/thread + 32KB smem loses).
//           Gathers via cp.async.cg in TWO 2-point commit groups, processing
//           points 0-1 while 2-3 are in flight.

#define VOL     262144       // 64^3
#define MTOT    884736       // 96^3
#define NC1     63
#define NCPAD   64
#define NC3P    (63 * 63 * 64)   // 254,016 cells per batch (padded)
#define NCELLSP (8 * NC3P)       // 2,032,128

__device__ uint4 g_tab[NCELLSP];

__device__ __forceinline__ unsigned pack2(float a, float b) {
    __half2 h = __floats2half2_rn(a, b);
    return *reinterpret_cast<unsigned*>(&h);
}

// One thread per 4-cell quad; 16 quads per (b,i,j) row, unconditional.
// Pad cell 63 holds junk (never read: i2 <= 62); the +4 scalar read stays in y.
__global__ void __launch_bounds__(256) repack_kernel(const float* __restrict__ y)
{
    int id = blockIdx.x * blockDim.x + threadIdx.x;
    const int TOTAL = 8 * 63 * 63 * 16;      // 508,032
    if (id >= TOTAL) return;

    int kq = id & 15;
    int r  = id >> 4;                         // (b*63+i)*63+j
    int j  = r % 63;
    int ij = r / 63;
    int i  = ij % 63;
    int b  = ij / 63;
    int k0 = kq * 4;

    const float* p0 = y + (size_t)b * VOL + i * 4096 + j * 64 + k0;
    const float* p1 = p0 + 64;
    const float* p2 = p0 + 4096;
    const float* p3 = p0 + 4160;

    float4 q0 = __ldg(reinterpret_cast<const float4*>(p0));
    float4 q1 = __ldg(reinterpret_cast<const float4*>(p1));
    float4 q2 = __ldg(reinterpret_cast<const float4*>(p2));
    float4 q3 = __ldg(reinterpret_cast<const float4*>(p3));
    float e0 = __ldg(p0 + 4);
    float e1 = __ldg(p1 + 4);
    float e2 = __ldg(p2 + 4);
    float e3 = __ldg(p3 + 4);

    float a0[5] = {q0.x, q0.y, q0.z, q0.w, e0};
    float a1[5] = {q1.x, q1.y, q1.z, q1.w, e1};
    float a2[5] = {q2.x, q2.y, q2.z, q2.w, e2};
    float a3[5] = {q3.x, q3.y, q3.z, q3.w, e3};

    size_t cbase = (size_t)((b * 63 + i) * 63 + j) * NCPAD + k0;

#pragma unroll
    for (int c = 0; c < 4; c++) {
        uint4 cell;
        cell.x = pack2(a0[c], a0[c + 1]);   // v000, v001
        cell.y = pack2(a1[c], a1[c + 1]);   // v010, v011
        cell.z = pack2(a2[c], a2[c + 1]);   // v100, v101
        cell.w = pack2(a3[c], a3[c + 1]);   // v110, v111
        g_tab[cbase + c] = cell;
    }
}

__device__ __forceinline__ float lerp1(float a, float b, float t) {
    return fmaf(t, b - a, a);
}

__device__ __forceinline__ float2 h2f(unsigned u) {
    __half2 h = *reinterpret_cast<__half2*>(&u);
    return __half22float2(h);
}

__device__ __forceinline__ unsigned smem_u32(const void* p) {
    return (unsigned)__cvta_generic_to_shared(p);
}

__device__ __forceinline__ void gather_pt(const float* c, int p, int base,
                                          float* f0, float* f1, float* f2,
                                          uint4* stage, int tid)
{
    float r0 = c[3 * p + 0] * 63.0f;
    float r1 = c[3 * p + 1] * 63.0f;
    float r2 = c[3 * p + 2] * 63.0f;
    int i0 = min((int)r0, 62);
    int i1 = min((int)r1, 62);
    int i2 = min((int)r2, 62);
    f0[p] = r0 - (float)i0;
    f1[p] = r1 - (float)i1;
    f2[p] = r2 - (float)i2;
    int cell = base + ((i0 * NC1 + i1) << 6) + i2;
    unsigned saddr = smem_u32(&stage[p * 256 + tid]);
    const uint4* gptr = g_tab + cell;
    asm volatile("cp.async.cg.shared.global [%0], [%1], 16;"
                 :: "r"(saddr), "l"(gptr) : "memory");
}

__device__ __forceinline__ float lerp_tree(uint4 q, float f0, float f1, float f2)
{
    float2 e0 = h2f(q.x);   // v000, v001
    float2 e1 = h2f(q.y);   // v010, v011
    float2 e2 = h2f(q.z);   // v100, v101
    float2 e3 = h2f(q.w);   // v110, v111
    float v00 = lerp1(e0.x, e0.y, f2);
    float v01 = lerp1(e1.x, e1.y, f2);
    float v10 = lerp1(e2.x, e2.y, f2);
    float v11 = lerp1(e3.x, e3.y, f2);
    float v0  = lerp1(v00, v01, f1);
    float v1  = lerp1(v10, v11, f1);
    return lerp1(v0, v1, f0);
}

__global__ void __launch_bounds__(256) trilerp_kernel(
    const float* __restrict__ xn,
    float* __restrict__ out,
    int total4)
{
    __shared__ uint4 stage[4 * 256];          // 16 KB

    int tid = threadIdx.x;
    int t = blockIdx.x * 256 + tid;
    if (t >= total4) return;

    const float4* xv = reinterpret_cast<const float4*>(xn) + (size_t)t * 3;
    float4 A = __ldcs(xv + 0);
    float4 B = __ldcs(xv + 1);
    float4 C = __ldcs(xv + 2);
    float c[12] = {A.x, A.y, A.z, A.w,
                   B.x, B.y, B.z, B.w,
                   C.x, C.y, C.z, C.w};

    long long p0 = (long long)t * 4;
    int base = (int)(p0 / MTOT) * NC3P;

    float f0[4], f1[4], f2[4];

    // Group A: points 0,1
    gather_pt(c, 0, base, f0, f1, f2, stage, tid);
    gather_pt(c, 1, base, f0, f1, f2, stage, tid);
    asm volatile("cp.async.commit_group;");

    // Group B: points 2,3
    gather_pt(c, 2, base, f0, f1, f2, stage, tid);
    gather_pt(c, 3, base, f0, f1, f2, stage, tid);
    asm volatile("cp.async.commit_group;");

    float4 res;

    // Process group A while group B is in flight
    asm volatile("cp.async.wait_group 1;" ::: "memory");
    res.x = lerp_tree(stage[0 * 256 + tid], f0[0], f1[0], f2[0]);
    res.y = lerp_tree(stage[1 * 256 + tid], f0[1], f1[1], f2[1]);

    asm volatile("cp.async.wait_group 0;" ::: "memory");
    res.z = lerp_tree(stage[2 * 256 + tid], f0[2], f1[2], f2[2]);
    res.w = lerp_tree(stage[3 * 256 + tid], f0[3], f1[3], f2[3]);

    __stcs(reinterpret_cast<float4*>(out) + t, res);
}

extern "C" void kernel_launch(void* const* d_in, const int* in_sizes, int n_in,
                              void* d_out, int out_size)
{
    const float* y  = (const float*)d_in[0];   // (8, 64,64,64)
    const float* xn = (const float*)d_in[1];   // (8, 96^3, 3)
    float* out      = (float*)d_out;           // (8, 96^3)

    const int RTOTAL = 8 * 63 * 63 * 16;       // 508,032
    repack_kernel<<<(RTOTAL + 255) / 256, 256>>>(y);

    int total4 = out_size / 4;                 // 1,769,472
    trilerp_kernel<<<(total4 + 255) / 256, 256>>>(xn, out, total4);
}

// round 13
// speedup vs baseline: 1.6217x; 1.6217x over previous
#include <cuda_runtime.h>
#include <cuda_fp16.h>

// Trilinear interpolation, fp16 cell-table + cp.async gathers:
//   Pass 1 (repack): one block per (b,i) slab. Two x-planes staged in 32KB
//           smem (coalesced float4 loads, ~16MB total reads), cells packed
//           from smem, contiguous coalesced 16B stores (31.75MB).
//   Pass 2 (interp): EXACT R9 structure (proven 38.7us): 4 pts/thread,
//           4 cp.async.cg gathers in ONE commit group, one wait, smem stage.
//           R10/R11 showed any deviation (8pt/32KB smem, 2+2 split, padded
//           table) regresses.

#define VOL    262144        // 64^3
#define MTOT   884736        // 96^3
#define NC1    63
#define NC3    250047        // 63^3
#define NCELLS (8 * NC3)     // 2,000,376

// 32 MB static scratch table: one uint4 (8 x fp16) per cell
__device__ uint4 g_tab[NCELLS];

__device__ __forceinline__ unsigned pack2(float a, float b) {
    __half2 h = __floats2half2_rn(a, b);
    return *reinterpret_cast<unsigned*>(&h);
}

// One block per (b,i): stage planes i and i+1 of y[b] in smem, pack 63x63
// cells, write the contiguous 63.5KB cell range for this slab.
__global__ void __launch_bounds__(256) repack_kernel(const float* __restrict__ y)
{
    __shared__ float pl[2][4096];             // planes i, i+1 (64x64 each)

    int bi = blockIdx.x;                      // b*63 + i
    int b  = bi / 63;
    int i  = bi % 63;
    int tid = threadIdx.x;

    // Load 2 planes = 2048 float4s, 8 per thread, coalesced.
    const float4* src = reinterpret_cast<const float4*>(
        y + (size_t)b * VOL + (size_t)i * 4096);
#pragma unroll
    for (int v = 0; v < 8; v++) {
        int idx = v * 256 + tid;              // 0..2047
        reinterpret_cast<float4*>(&pl[0][0])[idx] = __ldg(src + idx);
    }
    __syncthreads();

    // Pack 3969 cells; cell c -> (j = c/63, k = c%63); output contiguous.
    uint4* dst = g_tab + (size_t)bi * 3969;
#pragma unroll
    for (int v = 0; v < 16; v++) {
        int c = v * 256 + tid;
        if (c < 3969) {
            int j = c / 63;
            int k = c - j * 63;
            const float* r0 = &pl[0][j * 64 + k];       // (i,   j)
            const float* r1 = r0 + 64;                  // (i,   j+1)
            const float* r2 = &pl[1][j * 64 + k];       // (i+1, j)
            const float* r3 = r2 + 64;                  // (i+1, j+1)
            uint4 cell;
            cell.x = pack2(r0[0], r0[1]);   // v000, v001
            cell.y = pack2(r1[0], r1[1]);   // v010, v011
            cell.z = pack2(r2[0], r2[1]);   // v100, v101
            cell.w = pack2(r3[0], r3[1]);   // v110, v111
            dst[c] = cell;
        }
    }
}

__device__ __forceinline__ float lerp1(float a, float b, float t) {
    return fmaf(t, b - a, a);
}

__device__ __forceinline__ float2 h2f(unsigned u) {
    __half2 h = *reinterpret_cast<__half2*>(&u);
    return __half22float2(h);
}

__device__ __forceinline__ unsigned smem_u32(const void* p) {
    return (unsigned)__cvta_generic_to_shared(p);
}

__global__ void __launch_bounds__(256) trilerp_kernel(
    const float* __restrict__ xn,
    float* __restrict__ out,
    int total4)
{
    __shared__ uint4 stage[4 * 256];          // 16 KB: stage[p*256 + tid]

    int tid = threadIdx.x;
    int t = blockIdx.x * 256 + tid;
    if (t >= total4) return;

    // streaming reads: evict-first so the gather table keeps L2
    const float4* xv = reinterpret_cast<const float4*>(xn) + (size_t)t * 3;
    float4 A = __ldcs(xv + 0);
    float4 B = __ldcs(xv + 1);
    float4 C = __ldcs(xv + 2);
    float c[12] = {A.x, A.y, A.z, A.w,
                   B.x, B.y, B.z, B.w,
                   C.x, C.y, C.z, C.w};

    long long p0 = (long long)t * 4;
    int b = (int)(p0 / MTOT);
    int base = b * NC3;

    // Phase 1: indices + fractions, fire cp.async gather per point immediately
    float f0[4], f1[4], f2[4];
#pragma unroll
    for (int p = 0; p < 4; p++) {
        float r0 = c[3 * p + 0] * 63.0f;
        float r1 = c[3 * p + 1] * 63.0f;
        float r2 = c[3 * p + 2] * 63.0f;
        int i0 = min((int)r0, 62);
        int i1 = min((int)r1, 62);
        int i2 = min((int)r2, 62);
        f0[p] = r0 - (float)i0;
        f1[p] = r1 - (float)i1;
        f2[p] = r2 - (float)i2;
        int cell = base + (i0 * NC1 + i1) * NC1 + i2;
        unsigned saddr = smem_u32(&stage[p * 256 + tid]);
        const uint4* gptr = g_tab + cell;
        asm volatile("cp.async.cg.shared.global [%0], [%1], 16;"
                     :: "r"(saddr), "l"(gptr) : "memory");
    }
    asm volatile("cp.async.commit_group;");
    asm volatile("cp.async.wait_group 0;" ::: "memory");

    // Phase 2: read own cells from smem (conflict-free: lanes consecutive 16B)
    float4 res;
    float* rp = &res.x;
#pragma unroll
    for (int p = 0; p < 4; p++) {
        uint4 q = stage[p * 256 + tid];
        float2 e0 = h2f(q.x);   // v000, v001
        float2 e1 = h2f(q.y);   // v010, v011
        float2 e2 = h2f(q.z);   // v100, v101
        float2 e3 = h2f(q.w);   // v110, v111
        float v00 = lerp1(e0.x, e0.y, f2[p]);
        float v01 = lerp1(e1.x, e1.y, f2[p]);
        float v10 = lerp1(e2.x, e2.y, f2[p]);
        float v11 = lerp1(e3.x, e3.y, f2[p]);
        float v0  = lerp1(v00, v01, f1[p]);
        float v1  = lerp1(v10, v11, f1[p]);
        rp[p]     = lerp1(v0, v1, f0[p]);
    }

    __stcs(reinterpret_cast<float4*>(out) + t, res);
}

extern "C" void kernel_launch(void* const* d_in, const int* in_sizes, int n_in,
                              void* d_out, int out_size)
{
    const float* y  = (const float*)d_in[0];   // (8, 64,64,64)
    const float* xn = (const float*)d_in[1];   // (8, 96^3, 3)
    float* out      = (float*)d_out;           // (8, 96^3)

    repack_kernel<<<8 * 63, 256>>>(y);         // 504 blocks, one per (b,i)

    int total4 = out_size / 4;                 // 1,769,472
    trilerp_kernel<<<(total4 + 255) / 256, 256>>>(xn, out, total4);
}

// round 15
// speedup vs baseline: 1.6228x; 1.0007x over previous
#include <cuda_runtime.h>
#include <cuda_fp16.h>

// Trilinear interpolation, fp16 cell-table + cp.async gathers:
//   Pass 1 (repack): two blocks per (b,i) slab (j-halves), 1008 blocks.
//           33 rows x 2 planes staged in 16.9KB smem, contiguous 16B stores.
//   Pass 2 (interp): R9 structure (proven 38.4us): 4 pts/thread, 4
//           cp.async.cg gathers in ONE commit group, one wait, smem stage.
//           Only change: L2 evict_last policy on gathers so the 32MB table
//           stays L2-resident against the xnew/out streams.

#define VOL    262144        // 64^3
#define MTOT   884736        // 96^3
#define NC1    63
#define NC3    250047        // 63^3
#define NCELLS (8 * NC3)     // 2,000,376

// 32 MB static scratch table: one uint4 (8 x fp16) per cell
__device__ uint4 g_tab[NCELLS];

__device__ __forceinline__ unsigned pack2(float a, float b) {
    __half2 h = __floats2half2_rn(a, b);
    return *reinterpret_cast<unsigned*>(&h);
}

// Two blocks per (b,i): h=0 covers cell rows j=0..31, h=1 covers j=32..62.
// Each stages rows [j0, j0+32] of planes i and i+1 (33 rows x 64 floats x 2).
__global__ void __launch_bounds__(256) repack_kernel(const float* __restrict__ y)
{
    __shared__ float pl[2][33 * 64];          // 16.9 KB

    int blk = blockIdx.x;                     // 0..1007
    int h   = blk & 1;
    int bi  = blk >> 1;                       // b*63 + i
    int b   = bi / 63;
    int i   = bi % 63;
    int tid = threadIdx.x;
    int j0  = h * 32;
    int nj  = h ? 31 : 32;

    const float* base0 = y + (size_t)b * VOL + (size_t)i * 4096 + j0 * 64;
    // 33 rows * 64 floats = 2112 floats = 528 float4 per plane, coalesced.
    for (int v = tid; v < 528; v += 256) {
        reinterpret_cast<float4*>(&pl[0][0])[v] =
            __ldg(reinterpret_cast<const float4*>(base0) + v);
        reinterpret_cast<float4*>(&pl[1][0])[v] =
            __ldg(reinterpret_cast<const float4*>(base0 + 4096) + v);
    }
    __syncthreads();

    uint4* dst = g_tab + (size_t)bi * 3969 + j0 * 63;
    int ncells = nj * 63;
    for (int v = tid; v < ncells; v += 256) {
        int j = v / 63;
        int k = v - j * 63;
        const float* r0 = &pl[0][j * 64 + k];       // (i,   j0+j)
        const float* r1 = r0 + 64;                  // (i,   j0+j+1)
        const float* r2 = &pl[1][j * 64 + k];       // (i+1, j0+j)
        const float* r3 = r2 + 64;                  // (i+1, j0+j+1)
        uint4 cell;
        cell.x = pack2(r0[0], r0[1]);   // v000, v001
        cell.y = pack2(r1[0], r1[1]);   // v010, v011
        cell.z = pack2(r2[0], r2[1]);   // v100, v101
        cell.w = pack2(r3[0], r3[1]);   // v110, v111
        dst[v] = cell;
    }
}

__device__ __forceinline__ float lerp1(float a, float b, float t) {
    return fmaf(t, b - a, a);
}

__device__ __forceinline__ float2 h2f(unsigned u) {
    __half2 h = *reinterpret_cast<__half2*>(&u);
    return __half22float2(h);
}

__device__ __forceinline__ unsigned smem_u32(const void* p) {
    return (unsigned)__cvta_generic_to_shared(p);
}

__global__ void __launch_bounds__(256) trilerp_kernel(
    const float* __restrict__ xn,
    float* __restrict__ out,
    int total4)
{
    __shared__ uint4 stage[4 * 256];          // 16 KB: stage[p*256 + tid]

    int tid = threadIdx.x;
    int t = blockIdx.x * 256 + tid;
    if (t >= total4) return;

    // L2 policy: gathers evict_last (table stays resident vs streams)
    unsigned long long pol;
    asm volatile("createpolicy.fractional.L2::evict_last.b64 %0, 1.0;"
                 : "=l"(pol));

    // streaming reads: evict-first so the gather table keeps L2
    const float4* xv = reinterpret_cast<const float4*>(xn) + (size_t)t * 3;
    float4 A = __ldcs(xv + 0);
    float4 B = __ldcs(xv + 1);
    float4 C = __ldcs(xv + 2);
    float c[12] = {A.x, A.y, A.z, A.w,
                   B.x, B.y, B.z, B.w,
                   C.x, C.y, C.z, C.w};

    long long p0 = (long long)t * 4;
    int b = (int)(p0 / MTOT);
    int base = b * NC3;

    // Phase 1: indices + fractions, fire cp.async gather per point immediately
    float f0[4], f1[4], f2[4];
#pragma unroll
    for (int p = 0; p < 4; p++) {
        float r0 = c[3 * p + 0] * 63.0f;
        float r1 = c[3 * p + 1] * 63.0f;
        float r2 = c[3 * p + 2] * 63.0f;
        int i0 = min((int)r0, 62);
        int i1 = min((int)r1, 62);
        int i2 = min((int)r2, 62);
        f0[p] = r0 - (float)i0;
        f1[p] = r1 - (float)i1;
        f2[p] = r2 - (float)i2;
        int cell = base + (i0 * NC1 + i1) * NC1 + i2;
        unsigned saddr = smem_u32(&stage[p * 256 + tid]);
        const uint4* gptr = g_tab + cell;
        asm volatile("cp.async.cg.shared.global.L2::cache_hint [%0], [%1], 16, %2;"
                     :: "r"(saddr), "l"(gptr), "l"(pol) : "memory");
    }
    asm volatile("cp.async.commit_group;");
    asm volatile("cp.async.wait_group 0;" ::: "memory");

    // Phase 2: read own cells from smem (conflict-free: lanes consecutive 16B)
    float4 res;
    float* rp = &res.x;
#pragma unroll
    for (int p = 0; p < 4; p++) {
        uint4 q = stage[p * 256 + tid];
        float2 e0 = h2f(q.x);   // v000, v001
        float2 e1 = h2f(q.y);   // v010, v011
        float2 e2 = h2f(q.z);   // v100, v101
        float2 e3 = h2f(q.w);   // v110, v111
        float v00 = lerp1(e0.x, e0.y, f2[p]);
        float v01 = lerp1(e1.x, e1.y, f2[p]);
        float v10 = lerp1(e2.x, e2.y, f2[p]);
        float v11 = lerp1(e3.x, e3.y, f2[p]);
        float v0  = lerp1(v00, v01, f1[p]);
        float v1  = lerp1(v10, v11, f1[p]);
        rp[p]     = lerp1(v0, v1, f0[p]);
    }

    __stcs(reinterpret_cast<float4*>(out) + t, res);
}

extern "C" void kernel_launch(void* const* d_in, const int* in_sizes, int n_in,
                              void* d_out, int out_size)
{
    const float* y  = (const float*)d_in[0];   // (8, 64,64,64)
    const float* xn = (const float*)d_in[1];   // (8, 96^3, 3)
    float* out      = (float*)d_out;           // (8, 96^3)

    repack_kernel<<<2 * 8 * 63, 256>>>(y);     // 1008 blocks, 2 per (b,i)

    int total4 = out_size / 4;                 // 1,769,472
    trilerp_kernel<<<(total4 + 255) / 256, 256>>>(xn, out, total4);
}